// round 5
// baseline (speedup 1.0000x reference)
#include <cuda_runtime.h>
#include <cstddef>

#define BB 32
#define LL 1024
#define DD 64
#define QT 32
#define MC 64
#define NCH 16
#define F4S 17            // float4 row stride (68 floats)
#define FS  68            // float row stride
#define DSTR 98           // D tile float stride

// ---- smem float offsets ----
#define OFF_Q    0
#define OFF_QP   2176
#define OFF_K    4352
#define OFF_V    8704
#define OFF_PDW  13056
#define OFF_D    19584
#define OFF_P    22720
#define OFF_RED  24896
#define OFF_INV  25152
#define SMEM_FLOATS 25184

__device__ int g_mask_is_int32;
__device__ float g_inv[BB * LL];

__device__ __forceinline__ void fma2(unsigned long long& d,
                                     unsigned long long a,
                                     unsigned long long b) {
    asm("fma.rn.f32x2 %0, %1, %2, %0;" : "+l"(d) : "l"(a), "l"(b));
}
__device__ __forceinline__ unsigned long long add2(unsigned long long a,
                                                   unsigned long long b) {
    unsigned long long r;
    asm("add.rn.f32x2 %0, %1, %2;" : "=l"(r) : "l"(a), "l"(b));
    return r;
}
__device__ __forceinline__ void unpack2(unsigned long long v, float& a, float& b) {
    unsigned int lo, hi;
    asm("mov.b64 {%0,%1}, %2;" : "=r"(lo), "=r"(hi) : "l"(v));
    a = __uint_as_float(lo); b = __uint_as_float(hi);
}
__device__ __forceinline__ float hsum2(unsigned long long v) {
    float a, b; unpack2(v, a, b); return a + b;
}
__device__ __forceinline__ unsigned long long dup2(float x) {
    unsigned long long r; unsigned int xi = __float_as_uint(x);
    asm("mov.b64 %0, {%1, %1};" : "=l"(r) : "r"(xi));
    return r;
}

// Detect mask dtype: int32 (bytes at offset%4!=0 all zero) vs uint8 bool.
__global__ void detect_mask_kernel(const unsigned char* __restrict__ m)
{
    if (threadIdx.x == 0 && blockIdx.x == 0) {
        int nz = 0;
        for (int i = 0; i < 4096; i++)
            if ((i & 3) != 0 && m[i] != 0) nz++;
        g_mask_is_int32 = (nz == 0) ? 1 : 0;
    }
}

__global__ __launch_bounds__(256, 2)
void sdpa_rel_kernel(const float* __restrict__ qg,
                     const float* __restrict__ kg,
                     const float* __restrict__ vg,
                     const unsigned char* __restrict__ mg,
                     const float* __restrict__ pg,
                     const float* __restrict__ qpg,
                     float* __restrict__ out)
{
    extern __shared__ float smem[];
    float* q_s   = smem + OFF_Q;
    float* qp_s  = smem + OFF_QP;
    float* k_s   = smem + OFF_K;
    float* v_s   = smem + OFF_V;
    float* pdw_s = smem + OFF_PDW;
    float* D_s   = smem + OFF_D;
    float* p_s   = smem + OFF_P;
    float* red_s = smem + OFF_RED;
    float* inv_s = smem + OFF_INV;

    float4* q_s4   = (float4*)q_s;
    float4* qp_s4  = (float4*)qp_s;
    float4* k_s4   = (float4*)k_s;
    float4* v_s4   = (float4*)v_s;
    float4* pdw_s4 = (float4*)pdw_s;
    float4* p_s4   = (float4*)p_s;
    const ulonglong2* q_s2   = (const ulonglong2*)q_s;
    const ulonglong2* qp_s2  = (const ulonglong2*)qp_s;
    const ulonglong2* k_s2   = (const ulonglong2*)k_s;
    const ulonglong2* v_s2   = (const ulonglong2*)v_s;
    const ulonglong2* pdw_s2 = (const ulonglong2*)pdw_s;

    const int tid  = threadIdx.x;
    const int lane = tid & 31;
    const int w    = tid >> 5;
    const int dq   = lane & 15;       // phase-2 d quad
    const int half = lane >> 4;       // phase-2 ml half
    const int t0   = blockIdx.x * QT;
    const int b    = blockIdx.y;
    const int mask_is_int32 = g_mask_is_int32;

    // q / qp tiles, pre-scaled by 1/8
    {
        const float4* qsrc  = (const float4*)(qg  + ((size_t)b * LL + t0) * DD);
        const float4* qpsrc = (const float4*)(qpg + ((size_t)b * LL + t0) * DD);
        #pragma unroll
        for (int i = 0; i < 2; i++) {
            int it = tid + i * 256;
            int r = it >> 4, c = it & 15;
            float4 a = qsrc[it];
            a.x *= 0.125f; a.y *= 0.125f; a.z *= 0.125f; a.w *= 0.125f;
            q_s4[r * F4S + c] = a;
            float4 p = qpsrc[it];
            p.x *= 0.125f; p.y *= 0.125f; p.z *= 0.125f; p.w *= 0.125f;
            qp_s4[r * F4S + c] = p;
        }
    }

    const int jbase = 992 - t0;      // absolute pdpa row for local c=0 at m0=0
    const int c0 = w * 12;           // diag-GEMM column base for this warp
    const int nc = (95 - c0 < 12) ? (95 - c0) : 12;

    unsigned long long acc[4][2];    // O accumulators: 4 rows x (d pair-pairs)
    #pragma unroll
    for (int r = 0; r < 4; r++) { acc[r][0] = 0ull; acc[r][1] = 0ull; }
    float rowsum = 0.f;

    float4* attn4 = (float4*)(out + (size_t)BB * LL * DD);

    for (int ch = 0; ch < NCH; ch++) {
        const int m0 = ch * MC;
        __syncthreads();

        // ---- loads: K, V, pdpa window ----
        {
            const float4* ks = (const float4*)(kg + ((size_t)b * LL + m0) * DD);
            const float4* vs = (const float4*)(vg + ((size_t)b * LL + m0) * DD);
            #pragma unroll
            for (int i = 0; i < 4; i++) {
                int it = tid + i * 256;
                int r = it >> 4, c = it & 15;
                k_s4[r * F4S + c] = ks[it];
                v_s4[r * F4S + c] = vs[it];
            }
            const float4* ps = (const float4*)(pg + ((size_t)b * (2 * LL - 1) + (m0 + jbase)) * DD);
            for (int it = tid; it < 95 * 16; it += 256) {
                int r = it >> 4, c = it & 15;
                pdw_s4[r * F4S + c] = ps[it];
            }
        }
        // mask prefetch straight from gmem (per-thread: row=lane, cols w*8..+8)
        unsigned long long mbits = 0ull;
        uint4 ma = make_uint4(0,0,0,0), mb = make_uint4(0,0,0,0);
        if (mask_is_int32) {
            const uint4* mi = (const uint4*)((const int*)mg
                              + ((size_t)(b * LL + t0 + lane)) * LL + m0 + w * 8);
            ma = __ldg(mi); mb = __ldg(mi + 1);
        } else {
            mbits = __ldg((const unsigned long long*)(mg
                       + ((size_t)(b * LL + t0 + lane)) * LL + m0 + w * 8));
        }
        __syncthreads();

        // ---- diag GEMM: D[t=lane][c] = qp[lane] . pdw[c] ----
        {
            unsigned long long dacc[12];
            #pragma unroll
            for (int cc = 0; cc < 12; cc++) dacc[cc] = 0ull;
            #pragma unroll 4
            for (int dg = 0; dg < 16; dg++) {
                ulonglong2 qp2 = qp_s2[lane * F4S + dg];
                #pragma unroll
                for (int cc = 0; cc < 12; cc++) {
                    if (cc < nc) {
                        ulonglong2 pd2 = pdw_s2[(c0 + cc) * F4S + dg];
                        fma2(dacc[cc], qp2.x, pd2.x);
                        fma2(dacc[cc], qp2.y, pd2.y);
                    }
                }
            }
            #pragma unroll
            for (int cc = 0; cc < 12; cc++)
                if (cc < nc) D_s[lane * DSTR + c0 + cc] = hsum2(dacc[cc]);
        }

        // ---- content GEMM: rows=lane, cols=w*8+jj ----
        unsigned long long cacc[8];
        #pragma unroll
        for (int jj = 0; jj < 8; jj++) cacc[jj] = 0ull;
        #pragma unroll 4
        for (int dg = 0; dg < 16; dg++) {
            ulonglong2 q2 = q_s2[lane * F4S + dg];
            #pragma unroll
            for (int jj = 0; jj < 8; jj++) {
                ulonglong2 k2 = k_s2[(w * 8 + jj) * F4S + dg];
                fma2(cacc[jj], q2.x, k2.x);
                fma2(cacc[jj], q2.y, k2.y);
            }
        }
        __syncthreads();   // D_s visible to all

        // ---- epilogue: s = content + D, mask, exp, rowsum, p tile ----
        #pragma unroll
        for (int jj = 0; jj < 8; jj++) {
            unsigned int mraw;
            if (mask_is_int32)
                mraw = (jj < 4) ? (&ma.x)[jj] : (&mb.x)[jj - 4];
            else
                mraw = (unsigned int)((mbits >> (8 * jj)) & 0xffULL);
            float s = hsum2(cacc[jj]) + D_s[lane * DSTR + 31 - lane + w * 8 + jj];
            float p = mraw ? 0.f : __expf(s);
            rowsum += p;
            p_s[lane * FS + w * 8 + jj] = p;
        }
        __syncthreads();   // p_s ready

        // ---- attn writeback (unnormalized), coalesced from p tile ----
        #pragma unroll
        for (int i = 0; i < 2; i++) {
            int it = tid + i * 256;
            int r = it >> 4, c = it & 15;
            attn4[((size_t)(b * LL + t0 + r)) * 256 + (m0 >> 2) + c] = p_s4[r * F4S + c];
        }

        // ---- O accumulation: thread = (dq, half, w); rows w*4+rr ----
        const int rbase = w * 4;
        #pragma unroll
        for (int mlg = 0; mlg < 8; mlg++) {
            float4 pv0 = p_s4[(rbase + 0) * F4S + half * 8 + mlg];
            float4 pv1 = p_s4[(rbase + 1) * F4S + half * 8 + mlg];
            float4 pv2 = p_s4[(rbase + 2) * F4S + half * 8 + mlg];
            float4 pv3 = p_s4[(rbase + 3) * F4S + half * 8 + mlg];
            float pr0[4] = {pv0.x, pv0.y, pv0.z, pv0.w};
            float pr1[4] = {pv1.x, pv1.y, pv1.z, pv1.w};
            float pr2[4] = {pv2.x, pv2.y, pv2.z, pv2.w};
            float pr3[4] = {pv3.x, pv3.y, pv3.z, pv3.w};
            #pragma unroll
            for (int e = 0; e < 4; e++) {
                int ml = half * 32 + mlg * 4 + e;
                ulonglong2 vv = v_s2[ml * F4S + dq];
                unsigned long long p0 = dup2(pr0[e]);
                unsigned long long p1 = dup2(pr1[e]);
                unsigned long long p2 = dup2(pr2[e]);
                unsigned long long p3 = dup2(pr3[e]);
                fma2(acc[0][0], p0, vv.x); fma2(acc[0][1], p0, vv.y);
                fma2(acc[1][0], p1, vv.x); fma2(acc[1][1], p1, vv.y);
                fma2(acc[2][0], p2, vv.x); fma2(acc[2][1], p2, vv.y);
                fma2(acc[3][0], p3, vv.x); fma2(acc[3][1], p3, vv.y);
            }
        }
    }

    // ---- rowsum reduce across warps ----
    red_s[w * 32 + lane] = rowsum;
    __syncthreads();
    if (w == 0) {
        float s8 = 0.f;
        #pragma unroll
        for (int i = 0; i < 8; i++) s8 += red_s[i * 32 + lane];
        float inv = 1.0f / s8;
        inv_s[lane] = inv;
        g_inv[b * LL + t0 + lane] = inv;
    }
    __syncthreads();

    // ---- combine halves, scale, write O ----
    #pragma unroll
    for (int rr = 0; rr < 4; rr++) {
        unsigned long long s0 = add2(acc[rr][0],
                                     __shfl_xor_sync(0xffffffffu, acc[rr][0], 16));
        unsigned long long s1 = add2(acc[rr][1],
                                     __shfl_xor_sync(0xffffffffu, acc[rr][1], 16));
        if (half == 0) {
            int row = w * 4 + rr;
            float iv = inv_s[row];
            float o0, o1, o2, o3;
            unpack2(s0, o0, o1);
            unpack2(s1, o2, o3);
            float4 o = make_float4(o0 * iv, o1 * iv, o2 * iv, o3 * iv);
            ((float4*)out)[((size_t)(b * LL + t0 + row)) * 16 + dq] = o;
        }
    }
}

// Scale attn by per-row inverse sums.
__global__ __launch_bounds__(256)
void scale_attn_kernel(float* __restrict__ attn)
{
    int idx = blockIdx.x * 256 + threadIdx.x;   // float4 index
    int row = idx >> 8;                          // 256 float4 per row
    float iv = __ldg(&g_inv[row]);
    float4* a4 = (float4*)attn;
    float4 v = a4[idx];
    v.x *= iv; v.y *= iv; v.z *= iv; v.w *= iv;
    a4[idx] = v;
}

extern "C" void kernel_launch(void* const* d_in, const int* in_sizes, int n_in,
                              void* d_out, int out_size)
{
    int i_mask = 3, i_pdpa = 4;
    for (int i = 0; i < n_in; i++) {
        if (in_sizes[i] == BB * LL * LL)              i_mask = i;
        else if (in_sizes[i] == BB * (2*LL-1) * DD)   i_pdpa = i;
    }
    int small_idx[4]; int ns = 0;
    for (int i = 0; i < n_in && ns < 4; i++)
        if (i != i_mask && i != i_pdpa) small_idx[ns++] = i;

    const float*         q    = (const float*)d_in[small_idx[0]];
    const float*         k    = (const float*)d_in[small_idx[1]];
    const float*         v    = (const float*)d_in[small_idx[2]];
    const float*         qpos = (const float*)d_in[small_idx[3]];
    const unsigned char* mask = (const unsigned char*)d_in[i_mask];
    const float*         pdpa = (const float*)d_in[i_pdpa];
    float* out = (float*)d_out;

    size_t smem_bytes = (size_t)SMEM_FLOATS * sizeof(float);
    cudaFuncSetAttribute(sdpa_rel_kernel,
                         cudaFuncAttributeMaxDynamicSharedMemorySize,
                         (int)smem_bytes);

    detect_mask_kernel<<<1, 32>>>(mask);
    dim3 grid(LL / QT, BB);
    sdpa_rel_kernel<<<grid, 256, smem_bytes>>>(q, k, v, mask, pdpa, qpos, out);

    float* attn = out + (size_t)BB * LL * DD;
    scale_attn_kernel<<<(BB * LL * LL / 4) / 256, 256>>>(attn);
}

// round 6
// speedup vs baseline: 1.0915x; 1.0915x over previous
#include <cuda_runtime.h>
#include <cstddef>

#define BB 32
#define LL 1024
#define DD 64
#define QT 32
#define MC 64
#define NCH 16
#define F4S 17            // float4 row stride (68 floats)
#define FS  68            // float row stride
#define DSTR 98           // D tile float stride

// ---- smem float offsets ----
#define OFF_Q    0
#define OFF_QP   2176
#define OFF_K    4352
#define OFF_V    8704
#define OFF_PDW  13056
#define OFF_D    19584
#define OFF_P    22720
#define OFF_RED  24896
#define OFF_INV  25152
#define SMEM_FLOATS 25184

__device__ int g_mask_is_int32;

__device__ __forceinline__ void fma2(unsigned long long& d,
                                     unsigned long long a,
                                     unsigned long long b) {
    asm("fma.rn.f32x2 %0, %1, %2, %0;" : "+l"(d) : "l"(a), "l"(b));
}
__device__ __forceinline__ unsigned long long add2(unsigned long long a,
                                                   unsigned long long b) {
    unsigned long long r;
    asm("add.rn.f32x2 %0, %1, %2;" : "=l"(r) : "l"(a), "l"(b));
    return r;
}
__device__ __forceinline__ void unpack2(unsigned long long v, float& a, float& b) {
    unsigned int lo, hi;
    asm("mov.b64 {%0,%1}, %2;" : "=r"(lo), "=r"(hi) : "l"(v));
    a = __uint_as_float(lo); b = __uint_as_float(hi);
}
__device__ __forceinline__ float hsum2(unsigned long long v) {
    float a, b; unpack2(v, a, b); return a + b;
}
__device__ __forceinline__ unsigned long long dup2(float x) {
    unsigned long long r; unsigned int xi = __float_as_uint(x);
    asm("mov.b64 %0, {%1, %1};" : "=l"(r) : "r"(xi));
    return r;
}

// Parallel mask-dtype detect: int32 if all bytes at offset%4!=0 are zero over
// the first 4KB; uint8 bool otherwise. 256 threads, one uint4 each.
__global__ __launch_bounds__(256)
void detect_mask_kernel(const unsigned char* __restrict__ m)
{
    __shared__ int any_nz;
    if (threadIdx.x == 0) any_nz = 0;
    __syncthreads();
    uint4 v = __ldg((const uint4*)m + threadIdx.x);
    unsigned int nz = (v.x & 0xFFFFFF00u) | (v.y & 0xFFFFFF00u)
                    | (v.z & 0xFFFFFF00u) | (v.w & 0xFFFFFF00u);
    if (nz) atomicOr(&any_nz, 1);
    __syncthreads();
    if (threadIdx.x == 0) g_mask_is_int32 = any_nz ? 0 : 1;
}

__global__ __launch_bounds__(256, 2)
void sdpa_rel_kernel(const float* __restrict__ qg,
                     const float* __restrict__ kg,
                     const float* __restrict__ vg,
                     const unsigned char* __restrict__ mg,
                     const float* __restrict__ pg,
                     const float* __restrict__ qpg,
                     float* __restrict__ out)
{
    extern __shared__ float smem[];
    float* q_s   = smem + OFF_Q;
    float* qp_s  = smem + OFF_QP;
    float* k_s   = smem + OFF_K;
    float* v_s   = smem + OFF_V;
    float* pdw_s = smem + OFF_PDW;
    float* D_s   = smem + OFF_D;
    float* p_s   = smem + OFF_P;
    float* red_s = smem + OFF_RED;
    float* inv_s = smem + OFF_INV;

    float4* q_s4   = (float4*)q_s;
    float4* qp_s4  = (float4*)qp_s;
    float4* k_s4   = (float4*)k_s;
    float4* v_s4   = (float4*)v_s;
    float4* pdw_s4 = (float4*)pdw_s;
    float4* p_s4   = (float4*)p_s;
    const ulonglong2* q_s2   = (const ulonglong2*)q_s;
    const ulonglong2* qp_s2  = (const ulonglong2*)qp_s;
    const ulonglong2* k_s2   = (const ulonglong2*)k_s;
    const ulonglong2* v_s2   = (const ulonglong2*)v_s;
    const ulonglong2* pdw_s2 = (const ulonglong2*)pdw_s;

    const int tid  = threadIdx.x;
    const int lane = tid & 31;
    const int w    = tid >> 5;
    const int dq   = lane & 15;       // phase-2 d quad
    const int half = lane >> 4;       // phase-2 ml half
    const int t0   = blockIdx.x * QT;
    const int b    = blockIdx.y;
    const int mask_is_int32 = g_mask_is_int32;

    // q / qp tiles, pre-scaled by 1/8
    {
        const float4* qsrc  = (const float4*)(qg  + ((size_t)b * LL + t0) * DD);
        const float4* qpsrc = (const float4*)(qpg + ((size_t)b * LL + t0) * DD);
        #pragma unroll
        for (int i = 0; i < 2; i++) {
            int it = tid + i * 256;
            int r = it >> 4, c = it & 15;
            float4 a = qsrc[it];
            a.x *= 0.125f; a.y *= 0.125f; a.z *= 0.125f; a.w *= 0.125f;
            q_s4[r * F4S + c] = a;
            float4 p = qpsrc[it];
            p.x *= 0.125f; p.y *= 0.125f; p.z *= 0.125f; p.w *= 0.125f;
            qp_s4[r * F4S + c] = p;
        }
    }

    const int jbase = 992 - t0;      // absolute pdpa row for local c=0 at m0=0
    const int c0 = w * 12;           // diag-GEMM column base for this warp

    unsigned long long acc[4][2];    // O accumulators: 4 rows x (d pair-pairs)
    #pragma unroll
    for (int r = 0; r < 4; r++) { acc[r][0] = 0ull; acc[r][1] = 0ull; }
    float rowsum = 0.f;

    float4* attn4 = (float4*)(out + (size_t)BB * LL * DD);

    for (int ch = 0; ch < NCH; ch++) {
        const int m0 = ch * MC;
        __syncthreads();

        // ---- loads: K, V, pdpa window ----
        {
            const float4* ks = (const float4*)(kg + ((size_t)b * LL + m0) * DD);
            const float4* vs = (const float4*)(vg + ((size_t)b * LL + m0) * DD);
            #pragma unroll
            for (int i = 0; i < 4; i++) {
                int it = tid + i * 256;
                int r = it >> 4, c = it & 15;
                k_s4[r * F4S + c] = ks[it];
                v_s4[r * F4S + c] = vs[it];
            }
            const float4* ps = (const float4*)(pg + ((size_t)b * (2 * LL - 1) + (m0 + jbase)) * DD);
            for (int it = tid; it < 95 * 16; it += 256) {
                int r = it >> 4, c = it & 15;
                pdw_s4[r * F4S + c] = ps[it];
            }
        }
        // mask prefetch straight from gmem (per-thread: row=lane, cols w*8..+8)
        unsigned long long mbits = 0ull;
        uint4 ma = make_uint4(0,0,0,0), mb = make_uint4(0,0,0,0);
        if (mask_is_int32) {
            const uint4* mi = (const uint4*)((const int*)mg
                              + ((size_t)(b * LL + t0 + lane)) * LL + m0 + w * 8);
            ma = __ldg(mi); mb = __ldg(mi + 1);
        } else {
            mbits = __ldg((const unsigned long long*)(mg
                       + ((size_t)(b * LL + t0 + lane)) * LL + m0 + w * 8));
        }
        __syncthreads();

        // ---- diag GEMM: D[t=lane][c] = qp[lane] . pdw[c] ----
        // Unconditional 12 cols/warp. Column 95 (warp 7, cc=11) multiplies
        // whatever sits in pdw_s row 95 (allocated smem) and is never read:
        // max consumed col = 31 - 0 + 63 = 94.
        {
            unsigned long long dacc[12];
            #pragma unroll
            for (int cc = 0; cc < 12; cc++) dacc[cc] = 0ull;
            #pragma unroll 4
            for (int dg = 0; dg < 16; dg++) {
                ulonglong2 qp2 = qp_s2[lane * F4S + dg];
                #pragma unroll
                for (int cc = 0; cc < 12; cc++) {
                    ulonglong2 pd2 = pdw_s2[(c0 + cc) * F4S + dg];
                    fma2(dacc[cc], qp2.x, pd2.x);
                    fma2(dacc[cc], qp2.y, pd2.y);
                }
            }
            #pragma unroll
            for (int cc = 0; cc < 12; cc++)
                D_s[lane * DSTR + c0 + cc] = hsum2(dacc[cc]);
        }

        // ---- content GEMM: rows=lane, cols=w*8+jj ----
        unsigned long long cacc[8];
        #pragma unroll
        for (int jj = 0; jj < 8; jj++) cacc[jj] = 0ull;
        #pragma unroll 4
        for (int dg = 0; dg < 16; dg++) {
            ulonglong2 q2 = q_s2[lane * F4S + dg];
            #pragma unroll
            for (int jj = 0; jj < 8; jj++) {
                ulonglong2 k2 = k_s2[(w * 8 + jj) * F4S + dg];
                fma2(cacc[jj], q2.x, k2.x);
                fma2(cacc[jj], q2.y, k2.y);
            }
        }
        __syncthreads();   // D_s visible to all

        // ---- epilogue: s = content + D, mask, exp, rowsum, p tile ----
        #pragma unroll
        for (int jj = 0; jj < 8; jj++) {
            unsigned int mraw;
            if (mask_is_int32)
                mraw = (jj < 4) ? (&ma.x)[jj] : (&mb.x)[jj - 4];
            else
                mraw = (unsigned int)((mbits >> (8 * jj)) & 0xffULL);
            float s = hsum2(cacc[jj]) + D_s[lane * DSTR + 31 - lane + w * 8 + jj];
            float p = mraw ? 0.f : __expf(s);
            rowsum += p;
            p_s[lane * FS + w * 8 + jj] = p;
        }
        __syncthreads();   // p_s ready

        // ---- attn writeback (unnormalized), coalesced from p tile ----
        #pragma unroll
        for (int i = 0; i < 2; i++) {
            int it = tid + i * 256;
            int r = it >> 4, c = it & 15;
            attn4[((size_t)(b * LL + t0 + r)) * 256 + (m0 >> 2) + c] = p_s4[r * F4S + c];
        }

        // ---- O accumulation: thread = (dq, half, w); rows w*4+rr ----
        const int rbase = w * 4;
        #pragma unroll
        for (int mlg = 0; mlg < 8; mlg++) {
            float4 pv0 = p_s4[(rbase + 0) * F4S + half * 8 + mlg];
            float4 pv1 = p_s4[(rbase + 1) * F4S + half * 8 + mlg];
            float4 pv2 = p_s4[(rbase + 2) * F4S + half * 8 + mlg];
            float4 pv3 = p_s4[(rbase + 3) * F4S + half * 8 + mlg];
            float pr0[4] = {pv0.x, pv0.y, pv0.z, pv0.w};
            float pr1[4] = {pv1.x, pv1.y, pv1.z, pv1.w};
            float pr2[4] = {pv2.x, pv2.y, pv2.z, pv2.w};
            float pr3[4] = {pv3.x, pv3.y, pv3.z, pv3.w};
            #pragma unroll
            for (int e = 0; e < 4; e++) {
                int ml = half * 32 + mlg * 4 + e;
                ulonglong2 vv = v_s2[ml * F4S + dq];
                unsigned long long p0 = dup2(pr0[e]);
                unsigned long long p1 = dup2(pr1[e]);
                unsigned long long p2 = dup2(pr2[e]);
                unsigned long long p3 = dup2(pr3[e]);
                fma2(acc[0][0], p0, vv.x); fma2(acc[0][1], p0, vv.y);
                fma2(acc[1][0], p1, vv.x); fma2(acc[1][1], p1, vv.y);
                fma2(acc[2][0], p2, vv.x); fma2(acc[2][1], p2, vv.y);
                fma2(acc[3][0], p3, vv.x); fma2(acc[3][1], p3, vv.y);
            }
        }
    }

    // ---- rowsum reduce across warps ----
    red_s[w * 32 + lane] = rowsum;
    __syncthreads();
    if (w == 0) {
        float s8 = 0.f;
        #pragma unroll
        for (int i = 0; i < 8; i++) s8 += red_s[i * 32 + lane];
        inv_s[lane] = 1.0f / s8;
    }
    __syncthreads();

    // ---- combine halves, scale, write O ----
    #pragma unroll
    for (int rr = 0; rr < 4; rr++) {
        unsigned long long s0 = add2(acc[rr][0],
                                     __shfl_xor_sync(0xffffffffu, acc[rr][0], 16));
        unsigned long long s1 = add2(acc[rr][1],
                                     __shfl_xor_sync(0xffffffffu, acc[rr][1], 16));
        if (half == 0) {
            int row = w * 4 + rr;
            float iv = inv_s[row];
            float o0, o1, o2, o3;
            unpack2(s0, o0, o1);
            unpack2(s1, o2, o3);
            float4 o = make_float4(o0 * iv, o1 * iv, o2 * iv, o3 * iv);
            ((float4*)out)[((size_t)(b * LL + t0 + row)) * 16 + dq] = o;
        }
    }

    // ---- in-block attn rescale: 32 rows x 256 float4, mostly L2-hot ----
    // __syncthreads above orders this block's earlier gmem attn writes.
    {
        float4* base = attn4 + ((size_t)(b * LL + t0)) * 256;
        #pragma unroll 4
        for (int i = 0; i < 32; i++) {
            float iv = inv_s[i];
            float4 a = base[(size_t)i * 256 + tid];
            a.x *= iv; a.y *= iv; a.z *= iv; a.w *= iv;
            base[(size_t)i * 256 + tid] = a;
        }
    }
}

extern "C" void kernel_launch(void* const* d_in, const int* in_sizes, int n_in,
                              void* d_out, int out_size)
{
    int i_mask = 3, i_pdpa = 4;
    for (int i = 0; i < n_in; i++) {
        if (in_sizes[i] == BB * LL * LL)              i_mask = i;
        else if (in_sizes[i] == BB * (2*LL-1) * DD)   i_pdpa = i;
    }
    int small_idx[4]; int ns = 0;
    for (int i = 0; i < n_in && ns < 4; i++)
        if (i != i_mask && i != i_pdpa) small_idx[ns++] = i;

    const float*         q    = (const float*)d_in[small_idx[0]];
    const float*         k    = (const float*)d_in[small_idx[1]];
    const float*         v    = (const float*)d_in[small_idx[2]];
    const float*         qpos = (const float*)d_in[small_idx[3]];
    const unsigned char* mask = (const unsigned char*)d_in[i_mask];
    const float*         pdpa = (const float*)d_in[i_pdpa];
    float* out = (float*)d_out;

    size_t smem_bytes = (size_t)SMEM_FLOATS * sizeof(float);
    cudaFuncSetAttribute(sdpa_rel_kernel,
                         cudaFuncAttributeMaxDynamicSharedMemorySize,
                         (int)smem_bytes);

    detect_mask_kernel<<<1, 256>>>(mask);
    dim3 grid(LL / QT, BB);
    sdpa_rel_kernel<<<grid, 256, smem_bytes>>>(q, k, v, mask, pdpa, qpos, out);
}

// round 7
// speedup vs baseline: 1.0949x; 1.0031x over previous
#include <cuda_runtime.h>
#include <cstddef>

#define BB 32
#define LL 1024
#define DD 64
#define QT 32
#define MC 64
#define NCH 16
#define F4S 17            // float4 row stride (68 floats)
#define FS  68            // float row stride
#define DSTR 98           // D tile float stride

// ---- smem float offsets ----
#define OFF_Q    0
#define OFF_QP   2176
#define OFF_K    4352
#define OFF_V    8704
#define OFF_PDW  13056
#define OFF_D    19584
#define OFF_P    22720
#define OFF_RED  24896
#define OFF_INV  25152
#define SMEM_FLOATS 25184

__device__ int g_mask_is_int32;

__device__ __forceinline__ void fma2(unsigned long long& d,
                                     unsigned long long a,
                                     unsigned long long b) {
    asm("fma.rn.f32x2 %0, %1, %2, %0;" : "+l"(d) : "l"(a), "l"(b));
}
__device__ __forceinline__ unsigned long long add2(unsigned long long a,
                                                   unsigned long long b) {
    unsigned long long r;
    asm("add.rn.f32x2 %0, %1, %2;" : "=l"(r) : "l"(a), "l"(b));
    return r;
}
__device__ __forceinline__ void unpack2(unsigned long long v, float& a, float& b) {
    unsigned int lo, hi;
    asm("mov.b64 {%0,%1}, %2;" : "=r"(lo), "=r"(hi) : "l"(v));
    a = __uint_as_float(lo); b = __uint_as_float(hi);
}
__device__ __forceinline__ float hsum2(unsigned long long v) {
    float a, b; unpack2(v, a, b); return a + b;
}
__device__ __forceinline__ unsigned long long dup2(float x) {
    unsigned long long r; unsigned int xi = __float_as_uint(x);
    asm("mov.b64 %0, {%1, %1};" : "=l"(r) : "r"(xi));
    return r;
}

// Parallel mask-dtype detect: int32 if all bytes at offset%4!=0 are zero over
// the first 4KB; uint8 bool otherwise. 256 threads, one uint4 each.
__global__ __launch_bounds__(256)
void detect_mask_kernel(const unsigned char* __restrict__ m)
{
    __shared__ int any_nz;
    if (threadIdx.x == 0) any_nz = 0;
    __syncthreads();
    uint4 v = __ldg((const uint4*)m + threadIdx.x);
    unsigned int nz = (v.x & 0xFFFFFF00u) | (v.y & 0xFFFFFF00u)
                    | (v.z & 0xFFFFFF00u) | (v.w & 0xFFFFFF00u);
    if (nz) atomicOr(&any_nz, 1);
    __syncthreads();
    if (threadIdx.x == 0) g_mask_is_int32 = any_nz ? 0 : 1;
}

__global__ __launch_bounds__(256, 2)
void sdpa_rel_kernel(const float* __restrict__ qg,
                     const float* __restrict__ kg,
                     const float* __restrict__ vg,
                     const unsigned char* __restrict__ mg,
                     const float* __restrict__ pg,
                     const float* __restrict__ qpg,
                     float* __restrict__ out)
{
    extern __shared__ float smem[];
    float* q_s   = smem + OFF_Q;
    float* qp_s  = smem + OFF_QP;
    float* k_s   = smem + OFF_K;
    float* v_s   = smem + OFF_V;
    float* pdw_s = smem + OFF_PDW;
    float* D_s   = smem + OFF_D;
    float* p_s   = smem + OFF_P;
    float* red_s = smem + OFF_RED;
    float* inv_s = smem + OFF_INV;

    float4* q_s4   = (float4*)q_s;
    float4* qp_s4  = (float4*)qp_s;
    float4* k_s4   = (float4*)k_s;
    float4* v_s4   = (float4*)v_s;
    float4* pdw_s4 = (float4*)pdw_s;
    float4* p_s4   = (float4*)p_s;
    const ulonglong2* q_s2   = (const ulonglong2*)q_s;
    const ulonglong2* qp_s2  = (const ulonglong2*)qp_s;
    const ulonglong2* k_s2   = (const ulonglong2*)k_s;
    const ulonglong2* v_s2   = (const ulonglong2*)v_s;
    const ulonglong2* pdw_s2 = (const ulonglong2*)pdw_s;

    const int tid  = threadIdx.x;
    const int lane = tid & 31;
    const int w    = tid >> 5;
    const int dq   = lane & 15;       // phase-2 d quad
    const int half = lane >> 4;       // phase-2 ml half
    const int t0   = blockIdx.x * QT;
    const int b    = blockIdx.y;
    const int mask_is_int32 = g_mask_is_int32;

    // q / qp tiles, pre-scaled by 1/8
    {
        const float4* qsrc  = (const float4*)(qg  + ((size_t)b * LL + t0) * DD);
        const float4* qpsrc = (const float4*)(qpg + ((size_t)b * LL + t0) * DD);
        #pragma unroll
        for (int i = 0; i < 2; i++) {
            int it = tid + i * 256;
            int r = it >> 4, c = it & 15;
            float4 a = qsrc[it];
            a.x *= 0.125f; a.y *= 0.125f; a.z *= 0.125f; a.w *= 0.125f;
            q_s4[r * F4S + c] = a;
            float4 p = qpsrc[it];
            p.x *= 0.125f; p.y *= 0.125f; p.z *= 0.125f; p.w *= 0.125f;
            qp_s4[r * F4S + c] = p;
        }
    }

    const int jbase = 992 - t0;      // absolute pdpa row for local c=0 at m0=0
    const int c0 = w * 12;           // diag-GEMM column base for this warp

    unsigned long long acc[4][2];    // O accumulators: 4 rows x (d pair-pairs)
    #pragma unroll
    for (int r = 0; r < 4; r++) { acc[r][0] = 0ull; acc[r][1] = 0ull; }
    float rowsum = 0.f;

    float4* attn4 = (float4*)(out + (size_t)BB * LL * DD);

    for (int ch = 0; ch < NCH; ch++) {
        const int m0 = ch * MC;
        __syncthreads();

        // ---- loads: K, V, pdpa window ----
        {
            const float4* ks = (const float4*)(kg + ((size_t)b * LL + m0) * DD);
            const float4* vs = (const float4*)(vg + ((size_t)b * LL + m0) * DD);
            #pragma unroll
            for (int i = 0; i < 4; i++) {
                int it = tid + i * 256;
                int r = it >> 4, c = it & 15;
                k_s4[r * F4S + c] = ks[it];
                v_s4[r * F4S + c] = vs[it];
            }
            const float4* ps = (const float4*)(pg + ((size_t)b * (2 * LL - 1) + (m0 + jbase)) * DD);
            for (int it = tid; it < 95 * 16; it += 256) {
                int r = it >> 4, c = it & 15;
                pdw_s4[r * F4S + c] = ps[it];
            }
        }
        // mask prefetch straight from gmem (per-thread: row=lane, cols w*8..+8)
        unsigned long long mbits = 0ull;
        uint4 ma = make_uint4(0,0,0,0), mb = make_uint4(0,0,0,0);
        if (mask_is_int32) {
            const uint4* mi = (const uint4*)((const int*)mg
                              + ((size_t)(b * LL + t0 + lane)) * LL + m0 + w * 8);
            ma = __ldg(mi); mb = __ldg(mi + 1);
        } else {
            mbits = __ldg((const unsigned long long*)(mg
                       + ((size_t)(b * LL + t0 + lane)) * LL + m0 + w * 8));
        }
        __syncthreads();

        // ---- diag GEMM: D[t=lane][c] = qp[lane] . pdw[c] ----
        // Unconditional 12 cols/warp. Column 95 (warp 7, cc=11) multiplies
        // whatever sits in pdw_s row 95 (allocated smem) and is never read:
        // max consumed col = 31 - 0 + 63 = 94.
        {
            unsigned long long dacc[12];
            #pragma unroll
            for (int cc = 0; cc < 12; cc++) dacc[cc] = 0ull;
            #pragma unroll 4
            for (int dg = 0; dg < 16; dg++) {
                ulonglong2 qp2 = qp_s2[lane * F4S + dg];
                #pragma unroll
                for (int cc = 0; cc < 12; cc++) {
                    ulonglong2 pd2 = pdw_s2[(c0 + cc) * F4S + dg];
                    fma2(dacc[cc], qp2.x, pd2.x);
                    fma2(dacc[cc], qp2.y, pd2.y);
                }
            }
            #pragma unroll
            for (int cc = 0; cc < 12; cc++)
                D_s[lane * DSTR + c0 + cc] = hsum2(dacc[cc]);
        }

        // ---- content GEMM: rows=lane, cols=w*8+jj ----
        unsigned long long cacc[8];
        #pragma unroll
        for (int jj = 0; jj < 8; jj++) cacc[jj] = 0ull;
        #pragma unroll 4
        for (int dg = 0; dg < 16; dg++) {
            ulonglong2 q2 = q_s2[lane * F4S + dg];
            #pragma unroll
            for (int jj = 0; jj < 8; jj++) {
                ulonglong2 k2 = k_s2[(w * 8 + jj) * F4S + dg];
                fma2(cacc[jj], q2.x, k2.x);
                fma2(cacc[jj], q2.y, k2.y);
            }
        }
        __syncthreads();   // D_s visible to all

        // ---- epilogue: s = content + D, mask, exp, rowsum, p tile ----
        #pragma unroll
        for (int jj = 0; jj < 8; jj++) {
            unsigned int mraw;
            if (mask_is_int32)
                mraw = (jj < 4) ? (&ma.x)[jj] : (&mb.x)[jj - 4];
            else
                mraw = (unsigned int)((mbits >> (8 * jj)) & 0xffULL);
            float s = hsum2(cacc[jj]) + D_s[lane * DSTR + 31 - lane + w * 8 + jj];
            float p = mraw ? 0.f : __expf(s);
            rowsum += p;
            p_s[lane * FS + w * 8 + jj] = p;
        }
        __syncthreads();   // p_s ready

        // ---- attn writeback (unnormalized), coalesced from p tile ----
        #pragma unroll
        for (int i = 0; i < 2; i++) {
            int it = tid + i * 256;
            int r = it >> 4, c = it & 15;
            attn4[((size_t)(b * LL + t0 + r)) * 256 + (m0 >> 2) + c] = p_s4[r * F4S + c];
        }

        // ---- O accumulation: thread = (dq, half, w); rows w*4+rr ----
        const int rbase = w * 4;
        #pragma unroll
        for (int mlg = 0; mlg < 8; mlg++) {
            float4 pv0 = p_s4[(rbase + 0) * F4S + half * 8 + mlg];
            float4 pv1 = p_s4[(rbase + 1) * F4S + half * 8 + mlg];
            float4 pv2 = p_s4[(rbase + 2) * F4S + half * 8 + mlg];
            float4 pv3 = p_s4[(rbase + 3) * F4S + half * 8 + mlg];
            float pr0[4] = {pv0.x, pv0.y, pv0.z, pv0.w};
            float pr1[4] = {pv1.x, pv1.y, pv1.z, pv1.w};
            float pr2[4] = {pv2.x, pv2.y, pv2.z, pv2.w};
            float pr3[4] = {pv3.x, pv3.y, pv3.z, pv3.w};
            #pragma unroll
            for (int e = 0; e < 4; e++) {
                int ml = half * 32 + mlg * 4 + e;
                ulonglong2 vv = v_s2[ml * F4S + dq];
                unsigned long long p0 = dup2(pr0[e]);
                unsigned long long p1 = dup2(pr1[e]);
                unsigned long long p2 = dup2(pr2[e]);
                unsigned long long p3 = dup2(pr3[e]);
                fma2(acc[0][0], p0, vv.x); fma2(acc[0][1], p0, vv.y);
                fma2(acc[1][0], p1, vv.x); fma2(acc[1][1], p1, vv.y);
                fma2(acc[2][0], p2, vv.x); fma2(acc[2][1], p2, vv.y);
                fma2(acc[3][0], p3, vv.x); fma2(acc[3][1], p3, vv.y);
            }
        }
    }

    // ---- rowsum reduce across warps ----
    red_s[w * 32 + lane] = rowsum;
    __syncthreads();
    if (w == 0) {
        float s8 = 0.f;
        #pragma unroll
        for (int i = 0; i < 8; i++) s8 += red_s[i * 32 + lane];
        inv_s[lane] = 1.0f / s8;
    }
    __syncthreads();

    // ---- combine halves, scale, write O ----
    #pragma unroll
    for (int rr = 0; rr < 4; rr++) {
        unsigned long long s0 = add2(acc[rr][0],
                                     __shfl_xor_sync(0xffffffffu, acc[rr][0], 16));
        unsigned long long s1 = add2(acc[rr][1],
                                     __shfl_xor_sync(0xffffffffu, acc[rr][1], 16));
        if (half == 0) {
            int row = w * 4 + rr;
            float iv = inv_s[row];
            float o0, o1, o2, o3;
            unpack2(s0, o0, o1);
            unpack2(s1, o2, o3);
            float4 o = make_float4(o0 * iv, o1 * iv, o2 * iv, o3 * iv);
            ((float4*)out)[((size_t)(b * LL + t0 + row)) * 16 + dq] = o;
        }
    }

    // ---- in-block attn rescale: 32 rows x 256 float4, mostly L2-hot ----
    // __syncthreads above orders this block's earlier gmem attn writes.
    {
        float4* base = attn4 + ((size_t)(b * LL + t0)) * 256;
        #pragma unroll 4
        for (int i = 0; i < 32; i++) {
            float iv = inv_s[i];
            float4 a = base[(size_t)i * 256 + tid];
            a.x *= iv; a.y *= iv; a.z *= iv; a.w *= iv;
            base[(size_t)i * 256 + tid] = a;
        }
    }
}

extern "C" void kernel_launch(void* const* d_in, const int* in_sizes, int n_in,
                              void* d_out, int out_size)
{
    int i_mask = 3, i_pdpa = 4;
    for (int i = 0; i < n_in; i++) {
        if (in_sizes[i] == BB * LL * LL)              i_mask = i;
        else if (in_sizes[i] == BB * (2*LL-1) * DD)   i_pdpa = i;
    }
    int small_idx[4]; int ns = 0;
    for (int i = 0; i < n_in && ns < 4; i++)
        if (i != i_mask && i != i_pdpa) small_idx[ns++] = i;

    const float*         q    = (const float*)d_in[small_idx[0]];
    const float*         k    = (const float*)d_in[small_idx[1]];
    const float*         v    = (const float*)d_in[small_idx[2]];
    const float*         qpos = (const float*)d_in[small_idx[3]];
    const unsigned char* mask = (const unsigned char*)d_in[i_mask];
    const float*         pdpa = (const float*)d_in[i_pdpa];
    float* out = (float*)d_out;

    size_t smem_bytes = (size_t)SMEM_FLOATS * sizeof(float);
    cudaFuncSetAttribute(sdpa_rel_kernel,
                         cudaFuncAttributeMaxDynamicSharedMemorySize,
                         (int)smem_bytes);

    detect_mask_kernel<<<1, 256>>>(mask);
    dim3 grid(LL / QT, BB);
    sdpa_rel_kernel<<<grid, 256, smem_bytes>>>(q, k, v, mask, pdpa, qpos, out);
}